// round 1
// baseline (speedup 1.0000x reference)
#include <cuda_runtime.h>
#include <cstdint>

// Problem constants
#define BB   2048
#define LL   128
#define VV   128
#define EE   32
#define DD   64
#define NCB  10

// Output layout (concatenated, float32):
//   char_logits [B,128,128]   = 33554432
//   puzzles     [B,30,30]     =  1843200
//   features    [B,30,30,64]  = 117964800
//   quantized_st[B,30,30,64]  = 117964800
//   vq_loss     scalar        = 1
#define N_LOGITS  33554432
#define OFF_PUZZ  33554432
#define OFF_FEAT  35397632
#define OFF_QST   153362432
#define OFF_LOSS  271327232

// Scratch (no allocation allowed)
__device__ int   g_codes[BB * 30];
__device__ float g_partial[BB];

// ---------------- Encoder shared layout (floats) ----------------
// X   [32][132]  : 4224   (input pos l at col l+1, halo zero)
// H1  [64][66]   : 4224   (pos t at col t+1, halo zero)
// H2  [64][32]   : 2048
// ENC [30][64]   : 1920
// CB  [10][64]   : 640
// DIST[30][10]   : 304 (padded)
// WB             : 12288
// BS             : 64
#define ENC_X    0
#define ENC_H1   4224
#define ENC_H2   8448
#define ENC_ENC  10496
#define ENC_CB   12416
#define ENC_DIST 13056
#define ENC_WB   13360
#define ENC_BS   25648
#define ENC_SMEM_FLOATS 25712
#define ENC_SMEM_BYTES  (ENC_SMEM_FLOATS * 4)

__global__ void __launch_bounds__(256, 2)
enc_kernel(const int* __restrict__ ti, const float* __restrict__ emb,
           const float* __restrict__ w1, const float* __restrict__ b1,
           const float* __restrict__ w2, const float* __restrict__ b2,
           const float* __restrict__ w3, const float* __restrict__ b3,
           const float* __restrict__ cb,
           float* __restrict__ out_feat, float* __restrict__ out_qst,
           float* __restrict__ out_puzz)
{
    extern __shared__ float s[];
    float* X   = s + ENC_X;
    float* H1  = s + ENC_H1;
    float* H2  = s + ENC_H2;
    float* ENC = s + ENC_ENC;
    float* CB  = s + ENC_CB;
    float* DIST= s + ENC_DIST;
    float* WB  = s + ENC_WB;
    float* BS  = s + ENC_BS;
    __shared__ int   codes_s[30];
    __shared__ float mind_s[30];

    const int tid = threadIdx.x;
    const int b   = blockIdx.x;

    // zero X and H1 (halos), load codebook, w1, b1
    for (int i = tid; i < 4224; i += 256) { X[i] = 0.f; H1[i] = 0.f; }
    for (int i = tid; i < 640; i += 256) CB[i] = cb[i];
    for (int i = tid; i < 6144; i += 256) WB[i] = w1[i];
    if (tid < 64) BS[tid] = b1[tid];
    __syncthreads();

    // gather embeddings: X[e][l+1] = emb[ti[l]*32 + e]
    const int* tirow = ti + b * LL;
    for (int i = tid; i < LL * EE; i += 256) {
        int l = i >> 5, e = i & 31;
        X[e * 132 + l + 1] = emb[tirow[l] * EE + e];
    }
    __syncthreads();

    // conv1: in [32][128] pad1 stride2 k3 -> out [64][64], ReLU.  2o x 8t per thread (256 threads)
    {
        int o0 = (tid & 31) * 2;
        int t0 = (tid >> 5) * 8;
        float acc0[8], acc1[8];
        float bb0 = BS[o0], bb1 = BS[o0 + 1];
        #pragma unroll
        for (int u = 0; u < 8; u++) { acc0[u] = bb0; acc1[u] = bb1; }
        for (int e = 0; e < 32; e++) {
            float xv[17];
            const float* xr = &X[e * 132 + 2 * t0];
            #pragma unroll
            for (int u = 0; u < 17; u++) xv[u] = xr[u];
            const float* wp0 = &WB[(o0 * 32 + e) * 3];
            const float* wp1 = &WB[((o0 + 1) * 32 + e) * 3];
            float a0 = wp0[0], a1 = wp0[1], a2 = wp0[2];
            float c0 = wp1[0], c1 = wp1[1], c2 = wp1[2];
            #pragma unroll
            for (int t = 0; t < 8; t++) {
                float x0 = xv[2*t], x1 = xv[2*t+1], x2 = xv[2*t+2];
                acc0[t] += a0*x0 + a1*x1 + a2*x2;
                acc1[t] += c0*x0 + c1*x1 + c2*x2;
            }
        }
        #pragma unroll
        for (int t = 0; t < 8; t++) {
            H1[o0 * 66 + t0 + t + 1]       = fmaxf(acc0[t], 0.f);
            H1[(o0 + 1) * 66 + t0 + t + 1] = fmaxf(acc1[t], 0.f);
        }
    }
    __syncthreads();

    // load w2, b2
    for (int i = tid; i < 12288; i += 256) WB[i] = w2[i];
    if (tid < 64) BS[tid] = b2[tid];
    __syncthreads();

    // conv2: in [64][64] pad1 stride2 k3 -> out [64][32], ReLU.  2o x 8t (128 threads)
    if (tid < 128) {
        int o0 = (tid & 31) * 2;
        int t0 = (tid >> 5) * 8;
        float acc0[8], acc1[8];
        float bb0 = BS[o0], bb1 = BS[o0 + 1];
        #pragma unroll
        for (int u = 0; u < 8; u++) { acc0[u] = bb0; acc1[u] = bb1; }
        for (int e = 0; e < 64; e++) {
            float xv[17];
            const float* xr = &H1[e * 66 + 2 * t0];
            #pragma unroll
            for (int u = 0; u < 17; u++) xv[u] = xr[u];
            const float* wp0 = &WB[(o0 * 64 + e) * 3];
            const float* wp1 = &WB[((o0 + 1) * 64 + e) * 3];
            float a0 = wp0[0], a1 = wp0[1], a2 = wp0[2];
            float c0 = wp1[0], c1 = wp1[1], c2 = wp1[2];
            #pragma unroll
            for (int t = 0; t < 8; t++) {
                float x0 = xv[2*t], x1 = xv[2*t+1], x2 = xv[2*t+2];
                acc0[t] += a0*x0 + a1*x1 + a2*x2;
                acc1[t] += c0*x0 + c1*x1 + c2*x2;
            }
        }
        #pragma unroll
        for (int t = 0; t < 8; t++) {
            H2[o0 * 32 + t0 + t]       = fmaxf(acc0[t], 0.f);
            H2[(o0 + 1) * 32 + t0 + t] = fmaxf(acc1[t], 0.f);
        }
    }
    __syncthreads();

    // load w3, b3
    for (int i = tid; i < 12288; i += 256) WB[i] = w3[i];
    if (tid < 64) BS[tid] = b3[tid];
    __syncthreads();

    // conv3: in [64][32] pad0 stride1 k3 -> out [64][30] (no relu), stored transposed ENC[t][o].
    // 2o x 5t (192 threads)
    if (tid < 192) {
        int o0 = (tid & 31) * 2;
        int t0 = (tid >> 5) * 5;
        float acc0[5], acc1[5];
        float bb0 = BS[o0], bb1 = BS[o0 + 1];
        #pragma unroll
        for (int u = 0; u < 5; u++) { acc0[u] = bb0; acc1[u] = bb1; }
        for (int e = 0; e < 64; e++) {
            float xv[7];
            const float* xr = &H2[e * 32 + t0];
            #pragma unroll
            for (int u = 0; u < 7; u++) xv[u] = xr[u];
            const float* wp0 = &WB[(o0 * 64 + e) * 3];
            const float* wp1 = &WB[((o0 + 1) * 64 + e) * 3];
            float a0 = wp0[0], a1 = wp0[1], a2 = wp0[2];
            float c0 = wp1[0], c1 = wp1[1], c2 = wp1[2];
            #pragma unroll
            for (int t = 0; t < 5; t++) {
                acc0[t] += a0*xv[t] + a1*xv[t+1] + a2*xv[t+2];
                acc1[t] += c0*xv[t] + c1*xv[t+1] + c2*xv[t+2];
            }
        }
        #pragma unroll
        for (int t = 0; t < 5; t++) {
            ENC[(t0 + t) * 64 + o0]     = acc0[t];
            ENC[(t0 + t) * 64 + o0 + 1] = acc1[t];
        }
    }
    __syncthreads();

    // VQ distances: 30 rows x 10 codes
    for (int idx = tid; idx < 300; idx += 256) {
        int i = idx / 10, c = idx - i * 10;
        const float* fe = &ENC[i * 64];
        const float* cc = &CB[c * 64];
        float acc = 0.f;
        #pragma unroll 8
        for (int d = 0; d < 64; d++) { float df = fe[d] - cc[d]; acc += df * df; }
        DIST[i * 10 + c] = acc;
    }
    __syncthreads();
    if (tid < 30) {
        float mv = DIST[tid * 10]; int mc = 0;
        #pragma unroll
        for (int c = 1; c < 10; c++) {
            float v = DIST[tid * 10 + c];
            if (v < mv) { mv = v; mc = c; }
        }
        codes_s[tid] = mc;
        mind_s[tid] = mv;
        g_codes[b * 30 + tid] = mc;
    }
    __syncthreads();
    if (tid == 0) {
        float acc = 0.f;
        #pragma unroll
        for (int i = 0; i < 30; i++) acc += mind_s[i];
        g_partial[b] = acc;
    }

    // ---- outputs: puzzles (codes as float), features (enc broadcast), quantized_st (codebook broadcast)
    float* puz = out_puzz + (size_t)b * 900;
    for (int idx = tid; idx < 900; idx += 256) puz[idx] = (float)codes_s[idx / 30];

    float4* feat4 = (float4*)out_feat + (size_t)b * 14400;  // 900*16
    float4* qst4  = (float4*)out_qst  + (size_t)b * 14400;
    const float4* enc4 = (const float4*)ENC;
    const float4* cb4  = (const float4*)CB;
    for (int idx = tid; idx < 14400; idx += 256) {
        int i = idx / 480;           // (30*16)
        int q = idx & 15;
        feat4[idx] = enc4[i * 16 + q];
        qst4[idx]  = cb4[codes_s[i] * 16 + q];
    }
}

// ---------------- Decoder shared layout (floats) ----------------
// F  [64][36]  : 2304   (pos i at col i+2, halo zero)
// G1 [64][36]  : 2304   (pos p at col p+1, halo zero)
// G2 [64][68]  : 4352   (pos p at col p+1, halo zero)
// G3 [32][132] : 4224
// WB           : 8192
// CB           : 640
// BS           : 64
// OB           : 128
#define DEC_F    0
#define DEC_G1   2304
#define DEC_G2   4608
#define DEC_G3   8960
#define DEC_WB   13184
#define DEC_CB   21376
#define DEC_BS   22016
#define DEC_OB   22080
#define DEC_SMEM_FLOATS 22208
#define DEC_SMEM_BYTES  (DEC_SMEM_FLOATS * 4)

__global__ void __launch_bounds__(256, 2)
dec_kernel(const float* __restrict__ cb,
           const float* __restrict__ dw1, const float* __restrict__ db1,
           const float* __restrict__ dw2, const float* __restrict__ db2,
           const float* __restrict__ dw3, const float* __restrict__ db3,
           const float* __restrict__ ow,  const float* __restrict__ ob,
           float* __restrict__ out_logits)
{
    extern __shared__ float s[];
    float* F  = s + DEC_F;
    float* G1 = s + DEC_G1;
    float* G2 = s + DEC_G2;
    float* G3 = s + DEC_G3;
    float* WB = s + DEC_WB;
    float* CB = s + DEC_CB;
    float* BS = s + DEC_BS;
    float* OB = s + DEC_OB;
    __shared__ int codes_s[30];

    const int tid = threadIdx.x;
    const int b   = blockIdx.x;

    // zero F, G1, G2 (halos included)
    for (int i = tid; i < 4352; i += 256) {
        if (i < 2304) { F[i] = 0.f; G1[i] = 0.f; }
        G2[i] = 0.f;
    }
    for (int i = tid; i < 640; i += 256) CB[i] = cb[i];
    if (tid < 30) codes_s[tid] = g_codes[b * 30 + tid];
    // w1 half 0 + b1
    for (int i = tid; i < 6144; i += 256) WB[i] = dw1[i];
    if (tid < 64) BS[tid] = db1[tid];
    __syncthreads();

    // build F[d][i+2] = codebook[code[i]][d]
    for (int idx = tid; idx < 64 * 30; idx += 256) {
        int d = idx / 30, i = idx - d * 30;
        F[d * 36 + i + 2] = CB[codes_s[i] * 64 + d];
    }
    __syncthreads();

    // convT1: in [64][30], stride1 pad0 k3 -> out [64][32], ReLU. 2o x 8t (128 threads), c split in halves
    int o0 = (tid & 31) * 2;
    int t0 = ((tid >> 5) & 3) * 8;
    bool act1 = tid < 128;
    float ac0[8], ac1[8];
    if (act1) {
        float bb0 = BS[o0], bb1 = BS[o0 + 1];
        #pragma unroll
        for (int u = 0; u < 8; u++) { ac0[u] = bb0; ac1[u] = bb1; }
        for (int c = 0; c < 32; c++) {
            float xv[10];
            const float* xr = &F[c * 36 + t0];
            #pragma unroll
            for (int u = 0; u < 10; u++) xv[u] = xr[u];
            const float* wp0 = &WB[(c * 64 + o0) * 3];
            const float* wp1 = &WB[(c * 64 + o0 + 1) * 3];
            float a0 = wp0[0], a1 = wp0[1], a2 = wp0[2];
            float c0 = wp1[0], c1 = wp1[1], c2 = wp1[2];
            #pragma unroll
            for (int t = 0; t < 8; t++) {  // p = t0+t-k -> xv[t+2-k]
                ac0[t] += a0*xv[t+2] + a1*xv[t+1] + a2*xv[t];
                ac1[t] += c0*xv[t+2] + c1*xv[t+1] + c2*xv[t];
            }
        }
    }
    __syncthreads();
    for (int i = tid; i < 6144; i += 256) WB[i] = dw1[6144 + i];
    __syncthreads();
    if (act1) {
        for (int c = 0; c < 32; c++) {
            float xv[10];
            const float* xr = &F[(c + 32) * 36 + t0];
            #pragma unroll
            for (int u = 0; u < 10; u++) xv[u] = xr[u];
            const float* wp0 = &WB[(c * 64 + o0) * 3];
            const float* wp1 = &WB[(c * 64 + o0 + 1) * 3];
            float a0 = wp0[0], a1 = wp0[1], a2 = wp0[2];
            float c0 = wp1[0], c1 = wp1[1], c2 = wp1[2];
            #pragma unroll
            for (int t = 0; t < 8; t++) {
                ac0[t] += a0*xv[t+2] + a1*xv[t+1] + a2*xv[t];
                ac1[t] += c0*xv[t+2] + c1*xv[t+1] + c2*xv[t];
            }
        }
        #pragma unroll
        for (int t = 0; t < 8; t++) {
            G1[o0 * 36 + t0 + t + 1]       = fmaxf(ac0[t], 0.f);
            G1[(o0 + 1) * 36 + t0 + t + 1] = fmaxf(ac1[t], 0.f);
        }
    }
    __syncthreads();

    // convT2: in [64][32], stride2 pad1 k4 -> out [64][64], ReLU. 2o x 8t (256 threads), c halves
    {
        int oo = (tid & 31) * 2;
        int tt0 = (tid >> 5) * 8;   // even
        float b20[8], b21[8];
        // w2 half 0 + b2
        for (int i = tid; i < 8192; i += 256) WB[i] = dw2[i];
        if (tid < 64) BS[tid] = db2[tid];
        __syncthreads();
        {
            float bb0 = BS[oo], bb1 = BS[oo + 1];
            #pragma unroll
            for (int u = 0; u < 8; u++) { b20[u] = bb0; b21[u] = bb1; }
        }
        for (int half = 0; half < 2; half++) {
            if (half == 1) {
                __syncthreads();
                for (int i = tid; i < 8192; i += 256) WB[i] = dw2[8192 + i];
                __syncthreads();
            }
            int cbase = half * 32;
            for (int c = 0; c < 32; c++) {
                float xv[6];
                const float* xr = &G1[(c + cbase) * 36 + (tt0 >> 1)];
                #pragma unroll
                for (int u = 0; u < 6; u++) xv[u] = xr[u];
                const float* wp0 = &WB[(c * 64 + oo) * 4];
                const float* wp1 = &WB[(c * 64 + oo + 1) * 4];
                float a0 = wp0[0], a1 = wp0[1], a2 = wp0[2], a3 = wp0[3];
                float c0 = wp1[0], c1 = wp1[1], c2 = wp1[2], c3 = wp1[3];
                #pragma unroll
                for (int t = 0; t < 8; t++) {
                    int u1 = ((t + 1) >> 1) + 1;
                    float xh = xv[u1], xl = xv[u1 - 1];
                    if (t & 1) { // k1 = 0
                        b20[t] += a0 * xh + a2 * xl;
                        b21[t] += c0 * xh + c2 * xl;
                    } else {     // k1 = 1
                        b20[t] += a1 * xh + a3 * xl;
                        b21[t] += c1 * xh + c3 * xl;
                    }
                }
            }
        }
        #pragma unroll
        for (int t = 0; t < 8; t++) {
            G2[oo * 68 + tt0 + t + 1]       = fmaxf(b20[t], 0.f);
            G2[(oo + 1) * 68 + tt0 + t + 1] = fmaxf(b21[t], 0.f);
        }
    }
    __syncthreads();

    // convT3: in [64][64], stride2 pad1 k4 -> out [32][128], no relu. 2o x 8t (256 threads)
    {
        int oo = (tid & 15) * 2;
        int tt0 = (tid >> 4) * 8;   // even
        float b30[8], b31[8];
        for (int i = tid; i < 8192; i += 256) WB[i] = dw3[i];
        if (tid < 32) BS[tid] = db3[tid];
        __syncthreads();
        {
            float bb0 = BS[oo], bb1 = BS[oo + 1];
            #pragma unroll
            for (int u = 0; u < 8; u++) { b30[u] = bb0; b31[u] = bb1; }
        }
        for (int c = 0; c < 64; c++) {
            float xv[6];
            const float* xr = &G2[c * 68 + (tt0 >> 1)];
            #pragma unroll
            for (int u = 0; u < 6; u++) xv[u] = xr[u];
            const float* wp0 = &WB[(c * 32 + oo) * 4];
            const float* wp1 = &WB[(c * 32 + oo + 1) * 4];
            float a0 = wp0[0], a1 = wp0[1], a2 = wp0[2], a3 = wp0[3];
            float c0 = wp1[0], c1 = wp1[1], c2 = wp1[2], c3 = wp1[3];
            #pragma unroll
            for (int t = 0; t < 8; t++) {
                int u1 = ((t + 1) >> 1) + 1;
                float xh = xv[u1], xl = xv[u1 - 1];
                if (t & 1) {
                    b30[t] += a0 * xh + a2 * xl;
                    b31[t] += c0 * xh + c2 * xl;
                } else {
                    b30[t] += a1 * xh + a3 * xl;
                    b31[t] += c1 * xh + c3 * xl;
                }
            }
        }
        #pragma unroll
        for (int t = 0; t < 8; t++) {
            G3[oo * 132 + tt0 + t]       = b30[t];
            G3[(oo + 1) * 132 + tt0 + t] = b31[t];
        }
    }
    __syncthreads();

    // final GEMM: logits[l][v] = sum_e G3[e][l] * ow[v*32+e] + ob[v].  4v x 16l per thread
    {
        for (int i = tid; i < 4096; i += 256) WB[i] = ow[i];
        if (tid < 128) OB[tid] = ob[tid];
        __syncthreads();
        int v0 = (tid & 31) * 4;
        int l0 = (tid >> 5) * 16;
        float ga[4][16];
        #pragma unroll
        for (int j = 0; j < 4; j++) {
            float bj = OB[v0 + j];
            #pragma unroll
            for (int u = 0; u < 16; u++) ga[j][u] = bj;
        }
        for (int e = 0; e < 32; e++) {
            float xv[16];
            const float* xr = &G3[e * 132 + l0];
            #pragma unroll
            for (int u = 0; u < 16; u++) xv[u] = xr[u];
            float w0 = WB[(v0 + 0) * 32 + e];
            float w1 = WB[(v0 + 1) * 32 + e];
            float w2 = WB[(v0 + 2) * 32 + e];
            float w3 = WB[(v0 + 3) * 32 + e];
            #pragma unroll
            for (int u = 0; u < 16; u++) {
                float x = xv[u];
                ga[0][u] += w0 * x;
                ga[1][u] += w1 * x;
                ga[2][u] += w2 * x;
                ga[3][u] += w3 * x;
            }
        }
        float* outp = out_logits + ((size_t)b * 128 + l0) * 128 + v0;
        #pragma unroll
        for (int u = 0; u < 16; u++) {
            float4 vv = make_float4(ga[0][u], ga[1][u], ga[2][u], ga[3][u]);
            *(float4*)(outp + (size_t)u * 128) = vv;
        }
    }
}

// Deterministic loss reduce: fixed per-thread strided sums + tree reduce
__global__ void loss_kernel(float* __restrict__ out_loss)
{
    __shared__ float sm[256];
    float a = 0.f;
    for (int i = threadIdx.x; i < BB; i += 256) a += g_partial[i];
    sm[threadIdx.x] = a;
    __syncthreads();
    for (int sft = 128; sft > 0; sft >>= 1) {
        if (threadIdx.x < sft) sm[threadIdx.x] += sm[threadIdx.x + sft];
        __syncthreads();
    }
    if (threadIdx.x == 0)
        out_loss[0] = sm[0] * (1.25f / (2048.f * 30.f * 64.f));
}

extern "C" void kernel_launch(void* const* d_in, const int* in_sizes, int n_in,
                              void* d_out, int out_size)
{
    const int*   ti     = (const int*)  d_in[0];
    const float* emb    = (const float*)d_in[1];
    const float* enc_w1 = (const float*)d_in[2];
    const float* enc_b1 = (const float*)d_in[3];
    const float* enc_w2 = (const float*)d_in[4];
    const float* enc_b2 = (const float*)d_in[5];
    const float* enc_w3 = (const float*)d_in[6];
    const float* enc_b3 = (const float*)d_in[7];
    const float* cb     = (const float*)d_in[8];
    const float* dec_w1 = (const float*)d_in[9];
    const float* dec_b1 = (const float*)d_in[10];
    const float* dec_w2 = (const float*)d_in[11];
    const float* dec_b2 = (const float*)d_in[12];
    const float* dec_w3 = (const float*)d_in[13];
    const float* dec_b3 = (const float*)d_in[14];
    const float* out_w  = (const float*)d_in[15];
    const float* out_b  = (const float*)d_in[16];

    float* out        = (float*)d_out;
    float* out_logits = out;
    float* out_puzz   = out + OFF_PUZZ;
    float* out_feat   = out + OFF_FEAT;
    float* out_qst    = out + OFF_QST;
    float* out_loss   = out + OFF_LOSS;

    cudaFuncSetAttribute(enc_kernel, cudaFuncAttributeMaxDynamicSharedMemorySize, ENC_SMEM_BYTES);
    cudaFuncSetAttribute(dec_kernel, cudaFuncAttributeMaxDynamicSharedMemorySize, DEC_SMEM_BYTES);

    enc_kernel<<<BB, 256, ENC_SMEM_BYTES>>>(ti, emb, enc_w1, enc_b1, enc_w2, enc_b2,
                                            enc_w3, enc_b3, cb,
                                            out_feat, out_qst, out_puzz);
    dec_kernel<<<BB, 256, DEC_SMEM_BYTES>>>(cb, dec_w1, dec_b1, dec_w2, dec_b2,
                                            dec_w3, dec_b3, out_w, out_b, out_logits);
    loss_kernel<<<1, 256>>>(out_loss);
}